// round 11
// baseline (speedup 1.0000x reference)
#include <cuda_runtime.h>

#define D    2048
#define E    16
#define R    16
#define QO   2048
#define VO   512
#define NTOK 4096
#define SCALE 2.0f
#define TM   64
#define MAXT 80          // 4096/64 + 16
#define KSPL 4           // k_low K-split
#define RSPL 8           // router K-split

#define HP 36            // padded row stride (floats) for dd-major smem tiles
#define BSP 132          // delta B row stride (floats), 16B-multiple
#define LSP 66           // delta sL2 row stride (u64)

typedef unsigned long long u64;
typedef unsigned int u32;

__device__ __forceinline__ u64 pk2(float lo, float hi) {
    u64 r; asm("mov.b64 %0,{%1,%2};" : "=l"(r) : "f"(lo), "f"(hi)); return r;
}
__device__ __forceinline__ u64 fma2(u64 a, u64 b, u64 c) {
    u64 d; asm("fma.rn.f32x2 %0,%1,%2,%3;" : "=l"(d) : "l"(a), "l"(b), "l"(c)); return d;
}
__device__ __forceinline__ float2 upk(u64 v) {
    float2 f; asm("mov.b64 {%0,%1},%2;" : "=f"(f.x), "=f"(f.y) : "l"(v)); return f;
}
__device__ __forceinline__ u32 s2u(const void* p) {
    u32 a; asm("{ .reg .u64 t; cvta.to.shared.u64 t, %1; cvt.u32.u64 %0, t; }" : "=r"(a) : "l"(p));
    return a;
}
__device__ __forceinline__ void cpa16(u32 dst, const void* src) {
    asm volatile("cp.async.ca.shared.global [%0], [%1], 16;" :: "r"(dst), "l"(src) : "memory");
}
__device__ __forceinline__ void cpa_commit() { asm volatile("cp.async.commit_group;" ::: "memory"); }
__device__ __forceinline__ void cpa_wait1() { asm volatile("cp.async.wait_group 1;" ::: "memory"); }
__device__ __forceinline__ void cpa_wait0() { asm volatile("cp.async.wait_group 0;" ::: "memory"); }
__device__ __forceinline__ void red4(float* p, float4 v) {
    asm volatile("red.global.add.v4.f32 [%0], {%1,%2,%3,%4};"
                 :: "l"(p), "f"(v.x), "f"(v.y), "f"(v.z), "f"(v.w) : "memory");
}

// ---------------- scratch ----------------
__device__ float g_part[RSPL][NTOK][16];        // router K-split partial logits
__device__ int   g_top_idx[NTOK * 2];
__device__ float g_top_w[NTOK * 2];
__device__ int   g_cnt[2 * E];
__device__ int   g_fill[2 * E];
__device__ int   g_arrive;
__device__ int   g_perm[2][NTOK];
__device__ float g_lowp[KSPL][2][NTOK][32];     // unweighted low partials BY POSITION
__device__ float g_At[E][32][D];                // [e][col 0..15=q_r,16..31=v_r][d]

__device__ __forceinline__ void tile_lookup(const int* scnt, int tileId,
                                            int& e, int& base, int& nrows) {
    e = -1;
    int acc = 0, tacc = 0;
    #pragma unroll
    for (int i = 0; i < E; i++) {
        int c = scnt[i];
        int nt = (c + TM - 1) / TM;
        if (e < 0 && tileId >= tacc && tileId < tacc + nt) {
            e = i;
            base = acc + (tileId - tacc) * TM;
            nrows = min(TM, acc + c - base);
        }
        tacc += nt; acc += c;
    }
}

// ---------------- main: router GEMM (blocks 0..511) + prep (blocks 512..639) ----------
__global__ void __launch_bounds__(256) k_main(const float* __restrict__ h,
                                              const float* __restrict__ W,
                                              const float* __restrict__ qa,
                                              const float* __restrict__ va) {
    int b = blockIdx.x;
    int tid = threadIdx.x;

    __shared__ __align__(16) float sH[2][TM * HP];
    __shared__ __align__(16) float sW[2][16 * HP];
    __shared__ float tile[64][34];

    if (b >= 512) {
        // ---- prep role ----
        int pb = b - 512;               // 0..127
        if (pb == 0 && tid < 2 * E + 1) {
            if (tid < 2 * E) { g_cnt[tid] = 0; g_fill[tid] = 0; }
            else g_arrive = 0;
        }
        int e = pb & 15;
        int dbase = (pb >> 4) * 256;
        for (int d0 = dbase; d0 < dbase + 256; d0 += 64) {
            int row = tid >> 2, quad = tid & 3;
            float4 q4 = *(const float4*)(qa + ((size_t)e * D + d0 + row) * R + quad * 4);
            float4 v4 = *(const float4*)(va + ((size_t)e * D + d0 + row) * R + quad * 4);
            tile[row][quad * 4 + 0] = q4.x; tile[row][quad * 4 + 1] = q4.y;
            tile[row][quad * 4 + 2] = q4.z; tile[row][quad * 4 + 3] = q4.w;
            tile[row][16 + quad * 4 + 0] = v4.x; tile[row][16 + quad * 4 + 1] = v4.y;
            tile[row][16 + quad * 4 + 2] = v4.z; tile[row][16 + quad * 4 + 3] = v4.w;
            __syncthreads();
            int c = tid >> 3, seg = tid & 7;
            float* dst = &g_At[e][c][d0 + seg * 8];
            float4 w0 = make_float4(tile[seg * 8 + 0][c], tile[seg * 8 + 1][c],
                                    tile[seg * 8 + 2][c], tile[seg * 8 + 3][c]);
            float4 w1 = make_float4(tile[seg * 8 + 4][c], tile[seg * 8 + 5][c],
                                    tile[seg * 8 + 6][c], tile[seg * 8 + 7][c]);
            *(float4*)dst = w0;
            *(float4*)(dst + 4) = w1;
            __syncthreads();
        }
        return;
    }

    // ---- router role ----
    int tb = b & 63, s = b >> 6;
    int kbase = s * (D / RSPL);

    int hrow = tid >> 2, hq = tid & 3;
    int er = (tid >> 3) & 15, wq = tid & 7;
    bool wact = tid < 128;

    u32 sHa[2], sWa[2];
    #pragma unroll
    for (int bb = 0; bb < 2; bb++) {
        sHa[bb] = s2u(&sH[bb][hrow * HP + hq * 4]);
        sWa[bb] = s2u(&sW[bb][er * HP + wq * 4]);
    }
    const float* hsrc = h + (size_t)(tb * TM + hrow) * D + kbase + hq * 4;
    const float* wsrc = W + (size_t)er * D + kbase + wq * 4;

    cpa16(sHa[0], hsrc);
    cpa16(sHa[0] + 64, hsrc + 16);
    if (wact) cpa16(sWa[0], wsrc);
    cpa_commit();

    int trow = tid >> 3, j = tid & 7;
    int t0 = trow * 2, t1 = t0 + 1;
    u64 acc[2][2] = {{0ull, 0ull}, {0ull, 0ull}};

    int buf = 0;
    const int NCH = (D / RSPL) / 32;   // 8
    for (int c = 0; c < NCH; c++) {
        if (c + 1 < NCH) {
            int kc = (c + 1) * 32;
            cpa16(sHa[buf ^ 1], hsrc + kc);
            cpa16(sHa[buf ^ 1] + 64, hsrc + kc + 16);
            if (wact) cpa16(sWa[buf ^ 1], wsrc + kc);
            cpa_commit();
            cpa_wait1();
        } else {
            cpa_wait0();
        }
        __syncthreads();
        const float* Hb = &sH[buf][0];
        const float* Wb = &sW[buf][0];
        #pragma unroll
        for (int dd = 0; dd < 32; dd += 2) {
            u64 h0 = *(const u64*)&Hb[t0 * HP + dd];
            u64 h1 = *(const u64*)&Hb[t1 * HP + dd];
            u64 w0 = *(const u64*)&Wb[j * HP + dd];
            u64 w1 = *(const u64*)&Wb[(j + 8) * HP + dd];
            acc[0][0] = fma2(h0, w0, acc[0][0]);
            acc[0][1] = fma2(h0, w1, acc[0][1]);
            acc[1][0] = fma2(h1, w0, acc[1][0]);
            acc[1][1] = fma2(h1, w1, acc[1][1]);
        }
        __syncthreads();
        buf ^= 1;
    }

    #pragma unroll
    for (int i = 0; i < 2; i++) {
        int t = tb * TM + t0 + i;
        float2 a = upk(acc[i][0]);
        float2 bv = upk(acc[i][1]);
        g_part[s][t][j]     = a.x + a.y;
        g_part[s][t][j + 8] = bv.x + bv.y;
    }
}

// ---------------- route: softmax + top2 + histogram + spin-barrier + scatter ------
__global__ void __launch_bounds__(128) k_route(int n) {
    int t = blockIdx.x * 128 + threadIdx.x;
    int tid = threadIdx.x, lane = tid & 31;
    __shared__ int scnt[2 * E];

    int i0 = -1, i1 = -1;
    if (t < n) {
        float lg[E];
        #pragma unroll
        for (int c = 0; c < 4; c++) {
            float4 a = make_float4(0.f, 0.f, 0.f, 0.f);
            #pragma unroll
            for (int s = 0; s < RSPL; s++) {
                float4 p = *(const float4*)&g_part[s][t][c * 4];
                a.x += p.x; a.y += p.y; a.z += p.z; a.w += p.w;
            }
            lg[c * 4 + 0] = a.x; lg[c * 4 + 1] = a.y;
            lg[c * 4 + 2] = a.z; lg[c * 4 + 3] = a.w;
        }
        float m = lg[0];
        #pragma unroll
        for (int i = 1; i < E; i++) m = fmaxf(m, lg[i]);
        float ex[E], Z = 0.f;
        #pragma unroll
        for (int i = 0; i < E; i++) { ex[i] = expf(lg[i] - m); Z += ex[i]; }
        i0 = 0;
        #pragma unroll
        for (int i = 1; i < E; i++) if (lg[i] > lg[i0]) i0 = i;
        i1 = (i0 == 0) ? 1 : 0;
        #pragma unroll
        for (int i = 0; i < E; i++) if (i != i0 && lg[i] > lg[i1]) i1 = i;
        float p0 = ex[i0] / Z, p1 = ex[i1] / Z;
        float dn = p0 + p1 + 1e-20f;
        g_top_idx[t * 2]     = i0;
        g_top_idx[t * 2 + 1] = i1;
        g_top_w[t * 2]       = SCALE * p0 / dn;
        g_top_w[t * 2 + 1]   = SCALE * p1 / dn;
    }

    #pragma unroll
    for (int k = 0; k < 2; k++) {
        int key = (t < n) ? (k * E + ((k == 0) ? i0 : i1)) : -1;
        unsigned mask = __match_any_sync(0xffffffffu, key);
        int leader = __ffs(mask) - 1;
        if (key >= 0 && lane == leader) atomicAdd(&g_cnt[key], __popc(mask));
    }

    __threadfence();
    __syncthreads();
    if (tid == 0) {
        atomicAdd(&g_arrive, 1);
        while (atomicAdd(&g_arrive, 0) < (int)gridDim.x) { }
    }
    __syncthreads();

    if (tid < 2 * E) scnt[tid] = atomicAdd(&g_cnt[tid], 0);
    __syncthreads();

    #pragma unroll
    for (int k = 0; k < 2; k++) {
        int ei = (k == 0) ? i0 : i1;
        int key = (t < n) ? (k * E + ei) : -1;
        unsigned mask = __match_any_sync(0xffffffffu, key);
        int leader = __ffs(mask) - 1;
        int base = 0;
        if (key >= 0 && lane == leader) base = atomicAdd(&g_fill[key], __popc(mask));
        base = __shfl_sync(mask, base, leader);
        int rank = __popc(mask & ((1u << lane) - 1u));
        if (key >= 0) {
            int off = 0;
            #pragma unroll
            for (int i = 0; i < E; i++) if (i < ei) off += scnt[k * E + i];
            g_perm[k][off + base + rank] = t;
        }
    }
}

// ---------------- low projection (K-split 4, 128 threads, 4 tok x 4 col) ----------
__global__ void __launch_bounds__(128) k_low(const float* __restrict__ h) {
    int k = blockIdx.y;
    int s = blockIdx.z;
    int tileId = blockIdx.x;

    __shared__ int scnt[E];
    __shared__ __align__(16) float sH[2][TM * HP];
    __shared__ __align__(16) float sA[2][32 * HP];
    __shared__ int toks[TM];

    int tid = threadIdx.x;
    if (tid < E) scnt[tid] = g_cnt[k * E + tid];
    __syncthreads();

    int e, base, nrows;
    tile_lookup(scnt, tileId, e, base, nrows);
    if (e < 0) return;
    int kbase = s * (D / KSPL);

    if (tid < TM) toks[tid] = g_perm[k][base + ((tid < nrows) ? tid : 0)];
    __syncthreads();

    int srow = tid >> 3, sq = tid & 7;   // srow 0..15, sq 0..7

    u32 sHa[2][4], sAa[2][2];
    const float* hsrcs[4];
    #pragma unroll
    for (int i = 0; i < 4; i++) {
        int row = srow + 16 * i;
        hsrcs[i] = h + (size_t)toks[row] * D + kbase + sq * 4;
        sHa[0][i] = s2u(&sH[0][row * HP + sq * 4]);
        sHa[1][i] = s2u(&sH[1][row * HP + sq * 4]);
    }
    const float* asrc = &g_At[e][srow][kbase + sq * 4];
    #pragma unroll
    for (int i = 0; i < 2; i++) {
        int row = srow + 16 * i;
        sAa[0][i] = s2u(&sA[0][row * HP + sq * 4]);
        sAa[1][i] = s2u(&sA[1][row * HP + sq * 4]);
    }

    #pragma unroll
    for (int i = 0; i < 4; i++) cpa16(sHa[0][i], hsrcs[i]);
    cpa16(sAa[0][0], asrc);
    cpa16(sAa[0][1], asrc + 16 * D);
    cpa_commit();

    int trow = tid >> 3, j = tid & 7;
    int r0 = trow * 2, r1 = r0 + 1, r2 = r0 + 32, r3 = r2 + 1;

    u64 acc[4][4];
    #pragma unroll
    for (int i = 0; i < 4; i++)
        #pragma unroll
        for (int m = 0; m < 4; m++) acc[i][m] = 0ull;

    int buf = 0;
    const int NCH = (D / KSPL) / 32;   // 16
    for (int c = 0; c < NCH; c++) {
        if (c + 1 < NCH) {
            int kc = (c + 1) * 32;
            #pragma unroll
            for (int i = 0; i < 4; i++) cpa16(sHa[buf ^ 1][i], hsrcs[i] + kc);
            cpa16(sAa[buf ^ 1][0], asrc + kc);
            cpa16(sAa[buf ^ 1][1], asrc + 16 * D + kc);
            cpa_commit();
            cpa_wait1();
        } else {
            cpa_wait0();
        }
        __syncthreads();
        const float* Hb = &sH[buf][0];
        const float* Ab = &sA[buf][0];
        #pragma unroll
        for (int dd = 0; dd < 32; dd += 2) {
            u64 h0 = *(const u64*)&Hb[r0 * HP + dd];
            u64 h1 = *(const u64*)&Hb[r1 * HP + dd];
            u64 h2 = *(const u64*)&Hb[r2 * HP + dd];
            u64 h3 = *(const u64*)&Hb[r3 * HP + dd];
            u64 a0 = *(const u64*)&Ab[(j +  0) * HP + dd];
            u64 a1 = *(const u64*)&Ab[(j +  8) * HP + dd];
            u64 a2 = *(const u64*)&Ab[(j + 16) * HP + dd];
            u64 a3 = *(const u64*)&Ab[(j + 24) * HP + dd];
            acc[0][0] = fma2(h0, a0, acc[0][0]);
            acc[0][1] = fma2(h0, a1, acc[0][1]);
            acc[0][2] = fma2(h0, a2, acc[0][2]);
            acc[0][3] = fma2(h0, a3, acc[0][3]);
            acc[1][0] = fma2(h1, a0, acc[1][0]);
            acc[1][1] = fma2(h1, a1, acc[1][1]);
            acc[1][2] = fma2(h1, a2, acc[1][2]);
            acc[1][3] = fma2(h1, a3, acc[1][3]);
            acc[2][0] = fma2(h2, a0, acc[2][0]);
            acc[2][1] = fma2(h2, a1, acc[2][1]);
            acc[2][2] = fma2(h2, a2, acc[2][2]);
            acc[2][3] = fma2(h2, a3, acc[2][3]);
            acc[3][0] = fma2(h3, a0, acc[3][0]);
            acc[3][1] = fma2(h3, a1, acc[3][1]);
            acc[3][2] = fma2(h3, a2, acc[3][2]);
            acc[3][3] = fma2(h3, a3, acc[3][3]);
        }
        __syncthreads();
        buf ^= 1;
    }

    int rows[4] = {r0, r1, r2, r3};
    #pragma unroll
    for (int i = 0; i < 4; i++) {
        int row = rows[i];
        if (row < nrows) {
            int pos = base + row;
            #pragma unroll
            for (int m = 0; m < 4; m++) {
                float2 v = upk(acc[i][m]);
                g_lowp[s][k][pos][j + 8 * m] = v.x + v.y;
            }
        }
    }
}

// ---------------- delta: single-chunk blocks, grid (MAXT, 20) per pass ----------------
// y 0..15 -> q chunk y*128; y 16..19 -> v chunk (y-16)*128.
// Thread: 4 tokens (trow*4..+3) x 8 cols (tcol*8..+7). k=0 STG, k=1 red4.
__global__ void __launch_bounds__(256) k_delta(int k,
                                               const float* __restrict__ qb,
                                               const float* __restrict__ vb,
                                               float* __restrict__ out) {
    int tileId = blockIdx.x;

    __shared__ int scnt[E];
    __shared__ __align__(16) float sB[R * BSP];
    __shared__ __align__(16) u64 sL2[R * LSP];
    __shared__ int toks[TM];

    int tid = threadIdx.x;
    if (tid < E) scnt[tid] = g_cnt[k * E + tid];
    __syncthreads();

    int e, base, nrows;
    tile_lookup(scnt, tileId, e, base, nrows);
    if (e < 0) return;

    int y = blockIdx.y;
    const float* B; float* O; int ldB, cb, rbase;
    if (y < 16) {
        B = qb + (size_t)e * R * QO;
        O = out; ldB = QO; cb = y * 128; rbase = 0;
    } else {
        B = vb + (size_t)e * R * VO;
        O = out + (size_t)NTOK * QO; ldB = VO; cb = (y - 16) * 128; rbase = 16;
    }

    // stage B chunk: 16 r x 128 cols = 512 float4, 2 per thread
    {
        int br = tid >> 4, bq = tid & 15;
        u32 dst = s2u(&sB[br * BSP + bq * 4]);
        const float* bs = B + (size_t)br * ldB + cb + bq * 4;
        cpa16(dst, bs);
        cpa16(dst + 256, bs + 64);     // +64 floats = +256B smem
        cpa_commit();
    }

    if (tid < TM) toks[tid] = (tid < nrows) ? g_perm[k][base + tid] : 0;
    __syncthreads();

    // sL2 gather: 16 r x 64 tok, reduce K-splits, weight, store duplicated (v,v)
    #pragma unroll
    for (int i = 0; i < 4; i++) {
        int idx = tid + 256 * i;       // 0..1023
        int tok = idx & 63, r = idx >> 6;
        int pos = base + ((tok < nrows) ? tok : 0);
        int rq = rbase + r;
        float v = g_lowp[0][k][pos][rq] + g_lowp[1][k][pos][rq]
                + g_lowp[2][k][pos][rq] + g_lowp[3][k][pos][rq];
        v *= g_top_w[toks[tok] * 2 + k];
        sL2[r * LSP + tok] = pk2(v, v);
    }
    cpa_wait0();
    __syncthreads();

    int tcol = tid & 15;               // cols tcol*8 .. +7
    int trow = tid >> 4;               // tokens trow*4 .. +3
    int t4 = trow * 4;

    u64 acc[4][4];
    #pragma unroll
    for (int p = 0; p < 4; p++)
        #pragma unroll
        for (int jj = 0; jj < 4; jj++) acc[p][jj] = 0ull;

    #pragma unroll
    for (int r = 0; r < R; r++) {
        const u64* Br = (const u64*)&sB[r * BSP + tcol * 8];
        ulonglong2 q0 = *(const ulonglong2*)Br;         // cols 0..3 (2 u64)
        ulonglong2 q1 = *(const ulonglong2*)(Br + 2);   // cols 4..7
        #pragma unroll
        for (int p = 0; p < 4; p++) {
            u64 l = sL2[r * LSP + t4 + p];
            acc[p][0] = fma2(l, q0.x, acc[p][0]);
            acc[p][1] = fma2(l, q0.y, acc[p][1]);
            acc[p][2] = fma2(l, q1.x, acc[p][2]);
            acc[p][3] = fma2(l, q1.y, acc[p][3]);
        }
    }

    #pragma unroll
    for (int p = 0; p < 4; p++) {
        int row = t4 + p;
        if (row < nrows) {
            float2 u0 = upk(acc[p][0]), u1 = upk(acc[p][1]);
            float2 u2 = upk(acc[p][2]), u3 = upk(acc[p][3]);
            float4 v0 = make_float4(u0.x, u0.y, u1.x, u1.y);
            float4 v1 = make_float4(u2.x, u2.y, u3.x, u3.y);
            float* pt = O + (size_t)toks[row] * ldB + cb + tcol * 8;
            if (k == 0) {
                *(float4*)pt = v0;
                *(float4*)(pt + 4) = v1;
            } else {
                red4(pt, v0);
                red4(pt + 4, v1);
            }
        }
    }
}

// ---------------- launcher ----------------
extern "C" void kernel_launch(void* const* d_in, const int* in_sizes, int n_in,
                              void* d_out, int out_size) {
    const float* h  = (const float*)d_in[0];
    const float* W  = (const float*)d_in[1];
    const float* qa = (const float*)d_in[2];
    const float* qb = (const float*)d_in[3];
    const float* va = (const float*)d_in[4];
    const float* vb = (const float*)d_in[5];
    float* out = (float*)d_out;
    int n = in_sizes[0] / D;   // 4096

    k_main<<<640, 256>>>(h, W, qa, va);
    k_route<<<(n + 127) / 128, 128>>>(n);
    dim3 gb(MAXT, 2, KSPL);
    k_low<<<gb, 128>>>(h);
    dim3 gc(MAXT, 20);
    k_delta<<<gc, 256>>>(0, qb, vb, out);   // STG pass: writes every output
    k_delta<<<gc, 256>>>(1, qb, vb, out);   // RED pass: adds 2nd expert
}

// round 12
// speedup vs baseline: 1.2839x; 1.2839x over previous
#include <cuda_runtime.h>

#define D    2048
#define E    16
#define R    16
#define QO   2048
#define VO   512
#define NTOK 4096
#define SCALE 2.0f
#define TM   64
#define MAXT 80          // 4096/64 + 16
#define TMD  32          // delta tile tokens
#define MAXTD 144        // 4096/32 + 16
#define KSPL 4           // k_low K-split
#define RSPL 8           // router K-split

#define HP 36            // padded row stride (floats) for dd-major smem tiles
#define BSP 132          // delta B row stride (floats)
#define LPD 34           // delta sL row stride (floats)

typedef unsigned long long u64;
typedef unsigned int u32;

__device__ __forceinline__ u64 pk2(float lo, float hi) {
    u64 r; asm("mov.b64 %0,{%1,%2};" : "=l"(r) : "f"(lo), "f"(hi)); return r;
}
__device__ __forceinline__ u64 fma2(u64 a, u64 b, u64 c) {
    u64 d; asm("fma.rn.f32x2 %0,%1,%2,%3;" : "=l"(d) : "l"(a), "l"(b), "l"(c)); return d;
}
__device__ __forceinline__ float2 upk(u64 v) {
    float2 f; asm("mov.b64 {%0,%1},%2;" : "=f"(f.x), "=f"(f.y) : "l"(v)); return f;
}
__device__ __forceinline__ u32 s2u(const void* p) {
    u32 a; asm("{ .reg .u64 t; cvta.to.shared.u64 t, %1; cvt.u32.u64 %0, t; }" : "=r"(a) : "l"(p));
    return a;
}
__device__ __forceinline__ void cpa16(u32 dst, const void* src) {
    asm volatile("cp.async.ca.shared.global [%0], [%1], 16;" :: "r"(dst), "l"(src) : "memory");
}
__device__ __forceinline__ void cpa_commit() { asm volatile("cp.async.commit_group;" ::: "memory"); }
__device__ __forceinline__ void cpa_wait1() { asm volatile("cp.async.wait_group 1;" ::: "memory"); }
__device__ __forceinline__ void cpa_wait0() { asm volatile("cp.async.wait_group 0;" ::: "memory"); }
__device__ __forceinline__ void red4(float* p, float4 v) {
    asm volatile("red.global.add.v4.f32 [%0], {%1,%2,%3,%4};"
                 :: "l"(p), "f"(v.x), "f"(v.y), "f"(v.z), "f"(v.w) : "memory");
}

// ---------------- scratch ----------------
__device__ float g_part[RSPL][NTOK][16];        // router K-split partial logits
__device__ int   g_top_idx[NTOK * 2];
__device__ float g_top_w[NTOK * 2];
__device__ int   g_cnt[2 * E];
__device__ int   g_fill[2 * E];
__device__ int   g_arrive;
__device__ int   g_perm[2][NTOK];
__device__ float g_lowp[KSPL][2][NTOK][32];     // unweighted low partials BY POSITION
__device__ float g_At[E][32][D];                // [e][col 0..15=q_r,16..31=v_r][d]

__device__ __forceinline__ void tile_lookup64(const int* scnt, int tileId,
                                              int& e, int& base, int& nrows) {
    e = -1;
    int acc = 0, tacc = 0;
    #pragma unroll
    for (int i = 0; i < E; i++) {
        int c = scnt[i];
        int nt = (c + TM - 1) / TM;
        if (e < 0 && tileId >= tacc && tileId < tacc + nt) {
            e = i;
            base = acc + (tileId - tacc) * TM;
            nrows = min(TM, acc + c - base);
        }
        tacc += nt; acc += c;
    }
}
__device__ __forceinline__ void tile_lookup32(const int* scnt, int tileId,
                                              int& e, int& base, int& nrows) {
    e = -1;
    int acc = 0, tacc = 0;
    #pragma unroll
    for (int i = 0; i < E; i++) {
        int c = scnt[i];
        int nt = (c + TMD - 1) / TMD;
        if (e < 0 && tileId >= tacc && tileId < tacc + nt) {
            e = i;
            base = acc + (tileId - tacc) * TMD;
            nrows = min(TMD, acc + c - base);
        }
        tacc += nt; acc += c;
    }
}

// ---------------- main: router GEMM (blocks 0..511) + prep (blocks 512..639) ----------
__global__ void __launch_bounds__(256) k_main(const float* __restrict__ h,
                                              const float* __restrict__ W,
                                              const float* __restrict__ qa,
                                              const float* __restrict__ va) {
    int b = blockIdx.x;
    int tid = threadIdx.x;

    __shared__ __align__(16) float sH[2][TM * HP];
    __shared__ __align__(16) float sW[2][16 * HP];
    __shared__ float tile[64][34];

    if (b >= 512) {
        // ---- prep role ----
        int pb = b - 512;               // 0..127
        if (pb == 0 && tid < 2 * E + 1) {
            if (tid < 2 * E) { g_cnt[tid] = 0; g_fill[tid] = 0; }
            else g_arrive = 0;
        }
        int e = pb & 15;
        int dbase = (pb >> 4) * 256;
        for (int d0 = dbase; d0 < dbase + 256; d0 += 64) {
            int row = tid >> 2, quad = tid & 3;
            float4 q4 = *(const float4*)(qa + ((size_t)e * D + d0 + row) * R + quad * 4);
            float4 v4 = *(const float4*)(va + ((size_t)e * D + d0 + row) * R + quad * 4);
            tile[row][quad * 4 + 0] = q4.x; tile[row][quad * 4 + 1] = q4.y;
            tile[row][quad * 4 + 2] = q4.z; tile[row][quad * 4 + 3] = q4.w;
            tile[row][16 + quad * 4 + 0] = v4.x; tile[row][16 + quad * 4 + 1] = v4.y;
            tile[row][16 + quad * 4 + 2] = v4.z; tile[row][16 + quad * 4 + 3] = v4.w;
            __syncthreads();
            int c = tid >> 3, seg = tid & 7;
            float* dst = &g_At[e][c][d0 + seg * 8];
            float4 w0 = make_float4(tile[seg * 8 + 0][c], tile[seg * 8 + 1][c],
                                    tile[seg * 8 + 2][c], tile[seg * 8 + 3][c]);
            float4 w1 = make_float4(tile[seg * 8 + 4][c], tile[seg * 8 + 5][c],
                                    tile[seg * 8 + 6][c], tile[seg * 8 + 7][c]);
            *(float4*)dst = w0;
            *(float4*)(dst + 4) = w1;
            __syncthreads();
        }
        return;
    }

    // ---- router role ----
    int tb = b & 63, s = b >> 6;
    int kbase = s * (D / RSPL);

    int hrow = tid >> 2, hq = tid & 3;
    int er = (tid >> 3) & 15, wq = tid & 7;
    bool wact = tid < 128;

    u32 sHa[2], sWa[2];
    #pragma unroll
    for (int bb = 0; bb < 2; bb++) {
        sHa[bb] = s2u(&sH[bb][hrow * HP + hq * 4]);
        sWa[bb] = s2u(&sW[bb][er * HP + wq * 4]);
    }
    const float* hsrc = h + (size_t)(tb * TM + hrow) * D + kbase + hq * 4;
    const float* wsrc = W + (size_t)er * D + kbase + wq * 4;

    cpa16(sHa[0], hsrc);
    cpa16(sHa[0] + 64, hsrc + 16);
    if (wact) cpa16(sWa[0], wsrc);
    cpa_commit();

    int trow = tid >> 3, j = tid & 7;
    int t0 = trow * 2, t1 = t0 + 1;
    u64 acc[2][2] = {{0ull, 0ull}, {0ull, 0ull}};

    int buf = 0;
    const int NCH = (D / RSPL) / 32;   // 8
    for (int c = 0; c < NCH; c++) {
        if (c + 1 < NCH) {
            int kc = (c + 1) * 32;
            cpa16(sHa[buf ^ 1], hsrc + kc);
            cpa16(sHa[buf ^ 1] + 64, hsrc + kc + 16);
            if (wact) cpa16(sWa[buf ^ 1], wsrc + kc);
            cpa_commit();
            cpa_wait1();
        } else {
            cpa_wait0();
        }
        __syncthreads();
        const float* Hb = &sH[buf][0];
        const float* Wb = &sW[buf][0];
        #pragma unroll
        for (int dd = 0; dd < 32; dd += 2) {
            u64 h0 = *(const u64*)&Hb[t0 * HP + dd];
            u64 h1 = *(const u64*)&Hb[t1 * HP + dd];
            u64 w0 = *(const u64*)&Wb[j * HP + dd];
            u64 w1 = *(const u64*)&Wb[(j + 8) * HP + dd];
            acc[0][0] = fma2(h0, w0, acc[0][0]);
            acc[0][1] = fma2(h0, w1, acc[0][1]);
            acc[1][0] = fma2(h1, w0, acc[1][0]);
            acc[1][1] = fma2(h1, w1, acc[1][1]);
        }
        __syncthreads();
        buf ^= 1;
    }

    #pragma unroll
    for (int i = 0; i < 2; i++) {
        int t = tb * TM + t0 + i;
        float2 a = upk(acc[i][0]);
        float2 bv = upk(acc[i][1]);
        g_part[s][t][j]     = a.x + a.y;
        g_part[s][t][j + 8] = bv.x + bv.y;
    }
}

// ---------------- route: softmax + top2 + histogram + spin-barrier + scatter ------
__global__ void __launch_bounds__(128) k_route(int n) {
    int t = blockIdx.x * 128 + threadIdx.x;
    int tid = threadIdx.x, lane = tid & 31;
    __shared__ int scnt[2 * E];

    int i0 = -1, i1 = -1;
    if (t < n) {
        float lg[E];
        #pragma unroll
        for (int c = 0; c < 4; c++) {
            float4 a = make_float4(0.f, 0.f, 0.f, 0.f);
            #pragma unroll
            for (int s = 0; s < RSPL; s++) {
                float4 p = *(const float4*)&g_part[s][t][c * 4];
                a.x += p.x; a.y += p.y; a.z += p.z; a.w += p.w;
            }
            lg[c * 4 + 0] = a.x; lg[c * 4 + 1] = a.y;
            lg[c * 4 + 2] = a.z; lg[c * 4 + 3] = a.w;
        }
        float m = lg[0];
        #pragma unroll
        for (int i = 1; i < E; i++) m = fmaxf(m, lg[i]);
        float ex[E], Z = 0.f;
        #pragma unroll
        for (int i = 0; i < E; i++) { ex[i] = expf(lg[i] - m); Z += ex[i]; }
        i0 = 0;
        #pragma unroll
        for (int i = 1; i < E; i++) if (lg[i] > lg[i0]) i0 = i;
        i1 = (i0 == 0) ? 1 : 0;
        #pragma unroll
        for (int i = 0; i < E; i++) if (i != i0 && lg[i] > lg[i1]) i1 = i;
        float p0 = ex[i0] / Z, p1 = ex[i1] / Z;
        float dn = p0 + p1 + 1e-20f;
        g_top_idx[t * 2]     = i0;
        g_top_idx[t * 2 + 1] = i1;
        g_top_w[t * 2]       = SCALE * p0 / dn;
        g_top_w[t * 2 + 1]   = SCALE * p1 / dn;
    }

    #pragma unroll
    for (int k = 0; k < 2; k++) {
        int key = (t < n) ? (k * E + ((k == 0) ? i0 : i1)) : -1;
        unsigned mask = __match_any_sync(0xffffffffu, key);
        int leader = __ffs(mask) - 1;
        if (key >= 0 && lane == leader) atomicAdd(&g_cnt[key], __popc(mask));
    }

    __threadfence();
    __syncthreads();
    if (tid == 0) {
        atomicAdd(&g_arrive, 1);
        while (atomicAdd(&g_arrive, 0) < (int)gridDim.x) { }
    }
    __syncthreads();

    if (tid < 2 * E) scnt[tid] = atomicAdd(&g_cnt[tid], 0);
    __syncthreads();

    #pragma unroll
    for (int k = 0; k < 2; k++) {
        int ei = (k == 0) ? i0 : i1;
        int key = (t < n) ? (k * E + ei) : -1;
        unsigned mask = __match_any_sync(0xffffffffu, key);
        int leader = __ffs(mask) - 1;
        int base = 0;
        if (key >= 0 && lane == leader) base = atomicAdd(&g_fill[key], __popc(mask));
        base = __shfl_sync(mask, base, leader);
        int rank = __popc(mask & ((1u << lane) - 1u));
        if (key >= 0) {
            int off = 0;
            #pragma unroll
            for (int i = 0; i < E; i++) if (i < ei) off += scnt[k * E + i];
            g_perm[k][off + base + rank] = t;
        }
    }
}

// ---------------- low projection (K-split 4, 128 threads, 4 tok x 4 col) ----------
__global__ void __launch_bounds__(128) k_low(const float* __restrict__ h) {
    int k = blockIdx.y;
    int s = blockIdx.z;
    int tileId = blockIdx.x;

    __shared__ int scnt[E];
    __shared__ __align__(16) float sH[2][TM * HP];
    __shared__ __align__(16) float sA[2][32 * HP];
    __shared__ int toks[TM];

    int tid = threadIdx.x;
    if (tid < E) scnt[tid] = g_cnt[k * E + tid];
    __syncthreads();

    int e, base, nrows;
    tile_lookup64(scnt, tileId, e, base, nrows);
    if (e < 0) return;
    int kbase = s * (D / KSPL);

    if (tid < TM) toks[tid] = g_perm[k][base + ((tid < nrows) ? tid : 0)];
    __syncthreads();

    int srow = tid >> 3, sq = tid & 7;   // srow 0..15, sq 0..7

    u32 sHa[2][4], sAa[2][2];
    const float* hsrcs[4];
    #pragma unroll
    for (int i = 0; i < 4; i++) {
        int row = srow + 16 * i;
        hsrcs[i] = h + (size_t)toks[row] * D + kbase + sq * 4;
        sHa[0][i] = s2u(&sH[0][row * HP + sq * 4]);
        sHa[1][i] = s2u(&sH[1][row * HP + sq * 4]);
    }
    const float* asrc = &g_At[e][srow][kbase + sq * 4];
    #pragma unroll
    for (int i = 0; i < 2; i++) {
        int row = srow + 16 * i;
        sAa[0][i] = s2u(&sA[0][row * HP + sq * 4]);
        sAa[1][i] = s2u(&sA[1][row * HP + sq * 4]);
    }

    #pragma unroll
    for (int i = 0; i < 4; i++) cpa16(sHa[0][i], hsrcs[i]);
    cpa16(sAa[0][0], asrc);
    cpa16(sAa[0][1], asrc + 16 * D);
    cpa_commit();

    int trow = tid >> 3, j = tid & 7;
    int r0 = trow * 2, r1 = r0 + 1, r2 = r0 + 32, r3 = r2 + 1;

    u64 acc[4][4];
    #pragma unroll
    for (int i = 0; i < 4; i++)
        #pragma unroll
        for (int m = 0; m < 4; m++) acc[i][m] = 0ull;

    int buf = 0;
    const int NCH = (D / KSPL) / 32;   // 16
    for (int c = 0; c < NCH; c++) {
        if (c + 1 < NCH) {
            int kc = (c + 1) * 32;
            #pragma unroll
            for (int i = 0; i < 4; i++) cpa16(sHa[buf ^ 1][i], hsrcs[i] + kc);
            cpa16(sAa[buf ^ 1][0], asrc + kc);
            cpa16(sAa[buf ^ 1][1], asrc + 16 * D + kc);
            cpa_commit();
            cpa_wait1();
        } else {
            cpa_wait0();
        }
        __syncthreads();
        const float* Hb = &sH[buf][0];
        const float* Ab = &sA[buf][0];
        #pragma unroll
        for (int dd = 0; dd < 32; dd += 2) {
            u64 h0 = *(const u64*)&Hb[r0 * HP + dd];
            u64 h1 = *(const u64*)&Hb[r1 * HP + dd];
            u64 h2 = *(const u64*)&Hb[r2 * HP + dd];
            u64 h3 = *(const u64*)&Hb[r3 * HP + dd];
            u64 a0 = *(const u64*)&Ab[(j +  0) * HP + dd];
            u64 a1 = *(const u64*)&Ab[(j +  8) * HP + dd];
            u64 a2 = *(const u64*)&Ab[(j + 16) * HP + dd];
            u64 a3 = *(const u64*)&Ab[(j + 24) * HP + dd];
            acc[0][0] = fma2(h0, a0, acc[0][0]);
            acc[0][1] = fma2(h0, a1, acc[0][1]);
            acc[0][2] = fma2(h0, a2, acc[0][2]);
            acc[0][3] = fma2(h0, a3, acc[0][3]);
            acc[1][0] = fma2(h1, a0, acc[1][0]);
            acc[1][1] = fma2(h1, a1, acc[1][1]);
            acc[1][2] = fma2(h1, a2, acc[1][2]);
            acc[1][3] = fma2(h1, a3, acc[1][3]);
            acc[2][0] = fma2(h2, a0, acc[2][0]);
            acc[2][1] = fma2(h2, a1, acc[2][1]);
            acc[2][2] = fma2(h2, a2, acc[2][2]);
            acc[2][3] = fma2(h2, a3, acc[2][3]);
            acc[3][0] = fma2(h3, a0, acc[3][0]);
            acc[3][1] = fma2(h3, a1, acc[3][1]);
            acc[3][2] = fma2(h3, a2, acc[3][2]);
            acc[3][3] = fma2(h3, a3, acc[3][3]);
        }
        __syncthreads();
        buf ^= 1;
    }

    int rows[4] = {r0, r1, r2, r3};
    #pragma unroll
    for (int i = 0; i < 4; i++) {
        int row = rows[i];
        if (row < nrows) {
            int pos = base + row;
            #pragma unroll
            for (int m = 0; m < 4; m++) {
                float2 v = upk(acc[i][m]);
                g_lowp[s][k][pos][j + 8 * m] = v.x + v.y;
            }
        }
    }
}

// ---------------- delta: 32-token tiles, 2 chunks/block, grid (MAXTD, 10) ----------
// y 0..7 -> q chunk pair y*2; y 8..9 -> v chunk pair (y-8)*2. 128 threads.
// Warp w (0..3): tokens w*8..w*8+7; lane tcol: cols tcol*4..+3. k=0 STG, k=1 red4.
__global__ void __launch_bounds__(128) k_delta(int k,
                                               const float* __restrict__ qb,
                                               const float* __restrict__ vb,
                                               float* __restrict__ out) {
    int tileId = blockIdx.x;

    __shared__ int scnt[E];
    __shared__ __align__(16) float sB[2][R * BSP];
    __shared__ float sL[R * LPD];
    __shared__ int toks[TMD];

    int tid = threadIdx.x;
    if (tid < E) scnt[tid] = g_cnt[k * E + tid];
    __syncthreads();

    int e, base, nrows;
    tile_lookup32(scnt, tileId, e, base, nrows);
    if (e < 0) return;

    int y = blockIdx.y;
    const float* B; float* O; int ldB, ch0, rbase;
    if (y < 8) {
        B = qb + (size_t)e * R * QO;
        O = out; ldB = QO; ch0 = y * 2; rbase = 0;
    } else {
        B = vb + (size_t)e * R * VO;
        O = out + (size_t)NTOK * QO; ldB = VO; ch0 = (y - 8) * 2; rbase = 16;
    }

    // B staging: 16 r x 128 cols = 512 float4, 4 per thread
    int br = tid >> 3, bq = tid & 7;
    u32 sBa[2];
    sBa[0] = s2u(&sB[0][br * BSP + bq * 4]);
    sBa[1] = s2u(&sB[1][br * BSP + bq * 4]);
    const float* bsrc = B + (size_t)br * ldB + bq * 4;

    {
        const float* b0 = bsrc + ch0 * 128;
        cpa16(sBa[0],       b0);
        cpa16(sBa[0] + 128, b0 + 32);
        cpa16(sBa[0] + 256, b0 + 64);
        cpa16(sBa[0] + 384, b0 + 96);
        cpa_commit();
    }

    if (tid < TMD) toks[tid] = (tid < nrows) ? g_perm[k][base + tid] : 0;
    __syncthreads();

    // sL gather: 16 r x 32 tok, reduce K-splits + weight
    #pragma unroll
    for (int i = 0; i < 4; i++) {
        int idx = tid + 128 * i;          // 0..511
        int r = idx >> 5, row = idx & 31;
        int pos = base + ((row < nrows) ? row : 0);
        int rq = rbase + r;
        float v = g_lowp[0][k][pos][rq] + g_lowp[1][k][pos][rq]
                + g_lowp[2][k][pos][rq] + g_lowp[3][k][pos][rq];
        float w = g_top_w[toks[row] * 2 + k];
        sL[r * LPD + row] = v * w;
    }

    int w = tid >> 5;
    int tcol = tid & 31;
    int tb8 = w * 8;

    int buf = 0;
    for (int ci = 0; ci < 2; ci++) {
        if (ci + 1 < 2) {
            const float* b1 = bsrc + (ch0 + 1) * 128;
            cpa16(sBa[1],       b1);
            cpa16(sBa[1] + 128, b1 + 32);
            cpa16(sBa[1] + 256, b1 + 64);
            cpa16(sBa[1] + 384, b1 + 96);
            cpa_commit();
            cpa_wait1();
        } else {
            cpa_wait0();
        }
        __syncthreads();

        u64 acc[4][4];
        #pragma unroll
        for (int p = 0; p < 4; p++)
            #pragma unroll
            for (int jj = 0; jj < 4; jj++) acc[p][jj] = 0ull;

        const float* Bb = &sB[buf][0];
        #pragma unroll
        for (int r = 0; r < R; r++) {
            float4 b4 = *(const float4*)&Bb[r * BSP + tcol * 4];
            u64 b0 = pk2(b4.x, b4.x), b1 = pk2(b4.y, b4.y);
            u64 b2 = pk2(b4.z, b4.z), b3 = pk2(b4.w, b4.w);
            #pragma unroll
            for (int p = 0; p < 4; p++) {
                u64 l = *(const u64*)&sL[r * LPD + tb8 + 2 * p];
                acc[p][0] = fma2(l, b0, acc[p][0]);
                acc[p][1] = fma2(l, b1, acc[p][1]);
                acc[p][2] = fma2(l, b2, acc[p][2]);
                acc[p][3] = fma2(l, b3, acc[p][3]);
            }
        }

        int cbase = (ch0 + ci) * 128;
        #pragma unroll
        for (int p = 0; p < 4; p++) {
            float2 u0 = upk(acc[p][0]), u1 = upk(acc[p][1]);
            float2 u2 = upk(acc[p][2]), u3 = upk(acc[p][3]);
            #pragma unroll
            for (int half = 0; half < 2; half++) {
                int row = tb8 + 2 * p + half;
                if (row < nrows) {
                    float4 v = half == 0 ? make_float4(u0.x, u1.x, u2.x, u3.x)
                                         : make_float4(u0.y, u1.y, u2.y, u3.y);
                    float* pt = O + (size_t)toks[row] * ldB + cbase + tcol * 4;
                    if (k == 0) *(float4*)pt = v;
                    else        red4(pt, v);
                }
            }
        }
        __syncthreads();
        buf ^= 1;
    }
}

// ---------------- launcher ----------------
extern "C" void kernel_launch(void* const* d_in, const int* in_sizes, int n_in,
                              void* d_out, int out_size) {
    const float* h  = (const float*)d_in[0];
    const float* W  = (const float*)d_in[1];
    const float* qa = (const float*)d_in[2];
    const float* qb = (const float*)d_in[3];
    const float* va = (const float*)d_in[4];
    const float* vb = (const float*)d_in[5];
    float* out = (float*)d_out;
    int n = in_sizes[0] / D;   // 4096

    k_main<<<640, 256>>>(h, W, qa, va);
    k_route<<<(n + 127) / 128, 128>>>(n);
    dim3 gb(MAXT, 2, KSPL);
    k_low<<<gb, 128>>>(h);
    dim3 gc(MAXTD, 10);
    k_delta<<<gc, 128>>>(0, qb, vb, out);   // STG pass: writes every output
    k_delta<<<gc, 128>>>(1, qb, vb, out);   // RED pass: adds 2nd expert
}

// round 13
// speedup vs baseline: 1.4682x; 1.1435x over previous
#include <cuda_runtime.h>

#define D    2048
#define E    16
#define R    16
#define QO   2048
#define VO   512
#define NTOK 4096
#define SCALE 2.0f
#define TM   64
#define MAXT 80          // 4096/64 + 16
#define TMD  32          // delta tile tokens
#define MAXTD 144        // 4096/32 + 16
#define KSPL 4           // k_low K-split
#define RSPL 8           // router K-split

#define HP 36            // padded row stride (floats) for dd-major smem tiles
#define BSP 132          // delta B row stride (floats)
#define LPD 34           // delta sL row stride (floats)

typedef unsigned long long u64;
typedef unsigned int u32;

__device__ __forceinline__ u64 pk2(float lo, float hi) {
    u64 r; asm("mov.b64 %0,{%1,%2};" : "=l"(r) : "f"(lo), "f"(hi)); return r;
}
__device__ __forceinline__ u64 fma2(u64 a, u64 b, u64 c) {
    u64 d; asm("fma.rn.f32x2 %0,%1,%2,%3;" : "=l"(d) : "l"(a), "l"(b), "l"(c)); return d;
}
__device__ __forceinline__ float2 upk(u64 v) {
    float2 f; asm("mov.b64 {%0,%1},%2;" : "=f"(f.x), "=f"(f.y) : "l"(v)); return f;
}
__device__ __forceinline__ u32 s2u(const void* p) {
    u32 a; asm("{ .reg .u64 t; cvta.to.shared.u64 t, %1; cvt.u32.u64 %0, t; }" : "=r"(a) : "l"(p));
    return a;
}
__device__ __forceinline__ void cpa16(u32 dst, const void* src) {
    asm volatile("cp.async.ca.shared.global [%0], [%1], 16;" :: "r"(dst), "l"(src) : "memory");
}
__device__ __forceinline__ void cpa_commit() { asm volatile("cp.async.commit_group;" ::: "memory"); }
__device__ __forceinline__ void cpa_wait1() { asm volatile("cp.async.wait_group 1;" ::: "memory"); }
__device__ __forceinline__ void cpa_wait0() { asm volatile("cp.async.wait_group 0;" ::: "memory"); }
__device__ __forceinline__ void red4(float* p, float4 v) {
    asm volatile("red.global.add.v4.f32 [%0], {%1,%2,%3,%4};"
                 :: "l"(p), "f"(v.x), "f"(v.y), "f"(v.z), "f"(v.w) : "memory");
}

// ---------------- scratch ----------------
__device__ float g_part[RSPL][NTOK][16];        // router K-split partial logits
__device__ int   g_top_idx[NTOK * 2];
__device__ float g_top_w[NTOK * 2];
__device__ int   g_cnt[2 * E];
__device__ int   g_fill[2 * E];
__device__ int   g_arrive;
__device__ int   g_perm[2][NTOK];
__device__ float g_lowp[2][NTOK][32][KSPL];     // low partials, SPLIT FASTEST (float4-gatherable)
__device__ float g_At[E][32][D];                // [e][col 0..15=q_r,16..31=v_r][d]

__device__ __forceinline__ void tile_lookup64(const int* scnt, int tileId,
                                              int& e, int& base, int& nrows) {
    e = -1;
    int acc = 0, tacc = 0;
    #pragma unroll
    for (int i = 0; i < E; i++) {
        int c = scnt[i];
        int nt = (c + TM - 1) / TM;
        if (e < 0 && tileId >= tacc && tileId < tacc + nt) {
            e = i;
            base = acc + (tileId - tacc) * TM;
            nrows = min(TM, acc + c - base);
        }
        tacc += nt; acc += c;
    }
}
__device__ __forceinline__ void tile_lookup32(const int* scnt, int tileId,
                                              int& e, int& base, int& nrows) {
    e = -1;
    int acc = 0, tacc = 0;
    #pragma unroll
    for (int i = 0; i < E; i++) {
        int c = scnt[i];
        int nt = (c + TMD - 1) / TMD;
        if (e < 0 && tileId >= tacc && tileId < tacc + nt) {
            e = i;
            base = acc + (tileId - tacc) * TMD;
            nrows = min(TMD, acc + c - base);
        }
        tacc += nt; acc += c;
    }
}

// ---------------- main: router GEMM (blocks 0..511) + prep (blocks 512..639) ----------
__global__ void __launch_bounds__(256) k_main(const float* __restrict__ h,
                                              const float* __restrict__ W,
                                              const float* __restrict__ qa,
                                              const float* __restrict__ va) {
    int b = blockIdx.x;
    int tid = threadIdx.x;

    __shared__ __align__(16) float sH[2][TM * HP];
    __shared__ __align__(16) float sW[2][16 * HP];
    __shared__ float tile[64][34];

    if (b >= 512) {
        // ---- prep role ----
        int pb = b - 512;               // 0..127
        if (pb == 0 && tid < 2 * E + 1) {
            if (tid < 2 * E) { g_cnt[tid] = 0; g_fill[tid] = 0; }
            else g_arrive = 0;
        }
        int e = pb & 15;
        int dbase = (pb >> 4) * 256;
        for (int d0 = dbase; d0 < dbase + 256; d0 += 64) {
            int row = tid >> 2, quad = tid & 3;
            float4 q4 = *(const float4*)(qa + ((size_t)e * D + d0 + row) * R + quad * 4);
            float4 v4 = *(const float4*)(va + ((size_t)e * D + d0 + row) * R + quad * 4);
            tile[row][quad * 4 + 0] = q4.x; tile[row][quad * 4 + 1] = q4.y;
            tile[row][quad * 4 + 2] = q4.z; tile[row][quad * 4 + 3] = q4.w;
            tile[row][16 + quad * 4 + 0] = v4.x; tile[row][16 + quad * 4 + 1] = v4.y;
            tile[row][16 + quad * 4 + 2] = v4.z; tile[row][16 + quad * 4 + 3] = v4.w;
            __syncthreads();
            int c = tid >> 3, seg = tid & 7;
            float* dst = &g_At[e][c][d0 + seg * 8];
            float4 w0 = make_float4(tile[seg * 8 + 0][c], tile[seg * 8 + 1][c],
                                    tile[seg * 8 + 2][c], tile[seg * 8 + 3][c]);
            float4 w1 = make_float4(tile[seg * 8 + 4][c], tile[seg * 8 + 5][c],
                                    tile[seg * 8 + 6][c], tile[seg * 8 + 7][c]);
            *(float4*)dst = w0;
            *(float4*)(dst + 4) = w1;
            __syncthreads();
        }
        return;
    }

    // ---- router role ----
    int tb = b & 63, s = b >> 6;
    int kbase = s * (D / RSPL);

    int hrow = tid >> 2, hq = tid & 3;
    int er = (tid >> 3) & 15, wq = tid & 7;
    bool wact = tid < 128;

    u32 sHa[2], sWa[2];
    #pragma unroll
    for (int bb = 0; bb < 2; bb++) {
        sHa[bb] = s2u(&sH[bb][hrow * HP + hq * 4]);
        sWa[bb] = s2u(&sW[bb][er * HP + wq * 4]);
    }
    const float* hsrc = h + (size_t)(tb * TM + hrow) * D + kbase + hq * 4;
    const float* wsrc = W + (size_t)er * D + kbase + wq * 4;

    cpa16(sHa[0], hsrc);
    cpa16(sHa[0] + 64, hsrc + 16);
    if (wact) cpa16(sWa[0], wsrc);
    cpa_commit();

    int trow = tid >> 3, j = tid & 7;
    int t0 = trow * 2, t1 = t0 + 1;
    u64 acc[2][2] = {{0ull, 0ull}, {0ull, 0ull}};

    int buf = 0;
    const int NCH = (D / RSPL) / 32;   // 8
    for (int c = 0; c < NCH; c++) {
        if (c + 1 < NCH) {
            int kc = (c + 1) * 32;
            cpa16(sHa[buf ^ 1], hsrc + kc);
            cpa16(sHa[buf ^ 1] + 64, hsrc + kc + 16);
            if (wact) cpa16(sWa[buf ^ 1], wsrc + kc);
            cpa_commit();
            cpa_wait1();
        } else {
            cpa_wait0();
        }
        __syncthreads();
        const float* Hb = &sH[buf][0];
        const float* Wb = &sW[buf][0];
        #pragma unroll
        for (int dd = 0; dd < 32; dd += 2) {
            u64 h0 = *(const u64*)&Hb[t0 * HP + dd];
            u64 h1 = *(const u64*)&Hb[t1 * HP + dd];
            u64 w0 = *(const u64*)&Wb[j * HP + dd];
            u64 w1 = *(const u64*)&Wb[(j + 8) * HP + dd];
            acc[0][0] = fma2(h0, w0, acc[0][0]);
            acc[0][1] = fma2(h0, w1, acc[0][1]);
            acc[1][0] = fma2(h1, w0, acc[1][0]);
            acc[1][1] = fma2(h1, w1, acc[1][1]);
        }
        __syncthreads();
        buf ^= 1;
    }

    #pragma unroll
    for (int i = 0; i < 2; i++) {
        int t = tb * TM + t0 + i;
        float2 a = upk(acc[i][0]);
        float2 bv = upk(acc[i][1]);
        g_part[s][t][j]     = a.x + a.y;
        g_part[s][t][j + 8] = bv.x + bv.y;
    }
}

// ---------------- route: softmax + top2 + histogram + spin-barrier + scatter ------
__global__ void __launch_bounds__(128) k_route(int n) {
    int t = blockIdx.x * 128 + threadIdx.x;
    int tid = threadIdx.x, lane = tid & 31;
    __shared__ int scnt[2 * E];

    int i0 = -1, i1 = -1;
    if (t < n) {
        float lg[E];
        #pragma unroll
        for (int c = 0; c < 4; c++) {
            float4 a = make_float4(0.f, 0.f, 0.f, 0.f);
            #pragma unroll
            for (int s = 0; s < RSPL; s++) {
                float4 p = *(const float4*)&g_part[s][t][c * 4];
                a.x += p.x; a.y += p.y; a.z += p.z; a.w += p.w;
            }
            lg[c * 4 + 0] = a.x; lg[c * 4 + 1] = a.y;
            lg[c * 4 + 2] = a.z; lg[c * 4 + 3] = a.w;
        }
        float m = lg[0];
        #pragma unroll
        for (int i = 1; i < E; i++) m = fmaxf(m, lg[i]);
        float ex[E], Z = 0.f;
        #pragma unroll
        for (int i = 0; i < E; i++) { ex[i] = expf(lg[i] - m); Z += ex[i]; }
        i0 = 0;
        #pragma unroll
        for (int i = 1; i < E; i++) if (lg[i] > lg[i0]) i0 = i;
        i1 = (i0 == 0) ? 1 : 0;
        #pragma unroll
        for (int i = 0; i < E; i++) if (i != i0 && lg[i] > lg[i1]) i1 = i;
        float p0 = ex[i0] / Z, p1 = ex[i1] / Z;
        float dn = p0 + p1 + 1e-20f;
        g_top_idx[t * 2]     = i0;
        g_top_idx[t * 2 + 1] = i1;
        g_top_w[t * 2]       = SCALE * p0 / dn;
        g_top_w[t * 2 + 1]   = SCALE * p1 / dn;
    }

    #pragma unroll
    for (int k = 0; k < 2; k++) {
        int key = (t < n) ? (k * E + ((k == 0) ? i0 : i1)) : -1;
        unsigned mask = __match_any_sync(0xffffffffu, key);
        int leader = __ffs(mask) - 1;
        if (key >= 0 && lane == leader) atomicAdd(&g_cnt[key], __popc(mask));
    }

    __threadfence();
    __syncthreads();
    if (tid == 0) {
        atomicAdd(&g_arrive, 1);
        while (atomicAdd(&g_arrive, 0) < (int)gridDim.x) { }
    }
    __syncthreads();

    if (tid < 2 * E) scnt[tid] = atomicAdd(&g_cnt[tid], 0);
    __syncthreads();

    #pragma unroll
    for (int k = 0; k < 2; k++) {
        int ei = (k == 0) ? i0 : i1;
        int key = (t < n) ? (k * E + ei) : -1;
        unsigned mask = __match_any_sync(0xffffffffu, key);
        int leader = __ffs(mask) - 1;
        int base = 0;
        if (key >= 0 && lane == leader) base = atomicAdd(&g_fill[key], __popc(mask));
        base = __shfl_sync(mask, base, leader);
        int rank = __popc(mask & ((1u << lane) - 1u));
        if (key >= 0) {
            int off = 0;
            #pragma unroll
            for (int i = 0; i < E; i++) if (i < ei) off += scnt[k * E + i];
            g_perm[k][off + base + rank] = t;
        }
    }
}

// ---------------- low projection (K-split 4, 128 threads, 4 tok x 4 col) ----------
__global__ void __launch_bounds__(128) k_low(const float* __restrict__ h) {
    int k = blockIdx.y;
    int s = blockIdx.z;
    int tileId = blockIdx.x;

    __shared__ int scnt[E];
    __shared__ __align__(16) float sH[2][TM * HP];
    __shared__ __align__(16) float sA[2][32 * HP];
    __shared__ int toks[TM];

    int tid = threadIdx.x;
    if (tid < E) scnt[tid] = g_cnt[k * E + tid];
    __syncthreads();

    int e, base, nrows;
    tile_lookup64(scnt, tileId, e, base, nrows);
    if (e < 0) return;
    int kbase = s * (D / KSPL);

    if (tid < TM) toks[tid] = g_perm[k][base + ((tid < nrows) ? tid : 0)];
    __syncthreads();

    int srow = tid >> 3, sq = tid & 7;   // srow 0..15, sq 0..7

    u32 sHa[2][4], sAa[2][2];
    const float* hsrcs[4];
    #pragma unroll
    for (int i = 0; i < 4; i++) {
        int row = srow + 16 * i;
        hsrcs[i] = h + (size_t)toks[row] * D + kbase + sq * 4;
        sHa[0][i] = s2u(&sH[0][row * HP + sq * 4]);
        sHa[1][i] = s2u(&sH[1][row * HP + sq * 4]);
    }
    const float* asrc = &g_At[e][srow][kbase + sq * 4];
    #pragma unroll
    for (int i = 0; i < 2; i++) {
        int row = srow + 16 * i;
        sAa[0][i] = s2u(&sA[0][row * HP + sq * 4]);
        sAa[1][i] = s2u(&sA[1][row * HP + sq * 4]);
    }

    #pragma unroll
    for (int i = 0; i < 4; i++) cpa16(sHa[0][i], hsrcs[i]);
    cpa16(sAa[0][0], asrc);
    cpa16(sAa[0][1], asrc + 16 * D);
    cpa_commit();

    int trow = tid >> 3, j = tid & 7;
    int r0 = trow * 2, r1 = r0 + 1, r2 = r0 + 32, r3 = r2 + 1;

    u64 acc[4][4];
    #pragma unroll
    for (int i = 0; i < 4; i++)
        #pragma unroll
        for (int m = 0; m < 4; m++) acc[i][m] = 0ull;

    int buf = 0;
    const int NCH = (D / KSPL) / 32;   // 16
    for (int c = 0; c < NCH; c++) {
        if (c + 1 < NCH) {
            int kc = (c + 1) * 32;
            #pragma unroll
            for (int i = 0; i < 4; i++) cpa16(sHa[buf ^ 1][i], hsrcs[i] + kc);
            cpa16(sAa[buf ^ 1][0], asrc + kc);
            cpa16(sAa[buf ^ 1][1], asrc + 16 * D + kc);
            cpa_commit();
            cpa_wait1();
        } else {
            cpa_wait0();
        }
        __syncthreads();
        const float* Hb = &sH[buf][0];
        const float* Ab = &sA[buf][0];
        #pragma unroll
        for (int dd = 0; dd < 32; dd += 2) {
            u64 h0 = *(const u64*)&Hb[r0 * HP + dd];
            u64 h1 = *(const u64*)&Hb[r1 * HP + dd];
            u64 h2 = *(const u64*)&Hb[r2 * HP + dd];
            u64 h3 = *(const u64*)&Hb[r3 * HP + dd];
            u64 a0 = *(const u64*)&Ab[(j +  0) * HP + dd];
            u64 a1 = *(const u64*)&Ab[(j +  8) * HP + dd];
            u64 a2 = *(const u64*)&Ab[(j + 16) * HP + dd];
            u64 a3 = *(const u64*)&Ab[(j + 24) * HP + dd];
            acc[0][0] = fma2(h0, a0, acc[0][0]);
            acc[0][1] = fma2(h0, a1, acc[0][1]);
            acc[0][2] = fma2(h0, a2, acc[0][2]);
            acc[0][3] = fma2(h0, a3, acc[0][3]);
            acc[1][0] = fma2(h1, a0, acc[1][0]);
            acc[1][1] = fma2(h1, a1, acc[1][1]);
            acc[1][2] = fma2(h1, a2, acc[1][2]);
            acc[1][3] = fma2(h1, a3, acc[1][3]);
            acc[2][0] = fma2(h2, a0, acc[2][0]);
            acc[2][1] = fma2(h2, a1, acc[2][1]);
            acc[2][2] = fma2(h2, a2, acc[2][2]);
            acc[2][3] = fma2(h2, a3, acc[2][3]);
            acc[3][0] = fma2(h3, a0, acc[3][0]);
            acc[3][1] = fma2(h3, a1, acc[3][1]);
            acc[3][2] = fma2(h3, a2, acc[3][2]);
            acc[3][3] = fma2(h3, a3, acc[3][3]);
        }
        __syncthreads();
        buf ^= 1;
    }

    int rows[4] = {r0, r1, r2, r3};
    #pragma unroll
    for (int i = 0; i < 4; i++) {
        int row = rows[i];
        if (row < nrows) {
            int pos = base + row;
            #pragma unroll
            for (int m = 0; m < 4; m++) {
                float2 v = upk(acc[i][m]);
                g_lowp[k][pos][j + 8 * m][s] = v.x + v.y;   // split-fastest layout
            }
        }
    }
}

// ---------------- delta: 32-token tiles, 4 chunks/block, grid (MAXTD, 5) ----------
// y 0..3 -> q chunks y*4..+3; y=4 -> v chunks 0..3. 256 threads.
// Warp w (0..7): tokens w*4..+3; lane tcol: cols tcol*4..+3. k=0 STG, k=1 red4.
__global__ void __launch_bounds__(256) k_delta(int k,
                                               const float* __restrict__ qb,
                                               const float* __restrict__ vb,
                                               float* __restrict__ out) {
    int tileId = blockIdx.x;

    __shared__ int scnt[E];
    __shared__ __align__(16) float sB[2][R * BSP];
    __shared__ float sL[R * LPD];
    __shared__ int toks[TMD];

    int tid = threadIdx.x;
    if (tid < E) scnt[tid] = g_cnt[k * E + tid];
    __syncthreads();

    int e, base, nrows;
    tile_lookup32(scnt, tileId, e, base, nrows);
    if (e < 0) return;

    int y = blockIdx.y;
    const float* B; float* O; int ldB, ch0, rbase;
    if (y < 4) {
        B = qb + (size_t)e * R * QO;
        O = out; ldB = QO; ch0 = y * 4; rbase = 0;
    } else {
        B = vb + (size_t)e * R * VO;
        O = out + (size_t)NTOK * QO; ldB = VO; ch0 = 0; rbase = 16;
    }

    // B staging: 16 r x 128 cols = 512 float4, 2 per thread
    int br = tid >> 4, bq = tid & 15;
    u32 sBa[2];
    sBa[0] = s2u(&sB[0][br * BSP + bq * 4]);
    sBa[1] = s2u(&sB[1][br * BSP + bq * 4]);
    const float* bsrc = B + (size_t)br * ldB + bq * 4;

    cpa16(sBa[0],       bsrc + ch0 * 128);
    cpa16(sBa[0] + 256, bsrc + ch0 * 128 + 64);
    cpa_commit();

    if (tid < TMD) toks[tid] = (tid < nrows) ? g_perm[k][base + tid] : 0;
    __syncthreads();

    // sL gather: 16 r x 32 tok -> 512 elems, 2/thread, ONE LDG.128 each
    #pragma unroll
    for (int i = 0; i < 2; i++) {
        int idx = tid + 256 * i;          // 0..511
        int r = idx >> 5, row = idx & 31;
        int pos = base + ((row < nrows) ? row : 0);
        float4 p4 = *(const float4*)&g_lowp[k][pos][rbase + r][0];
        float v = (p4.x + p4.y) + (p4.z + p4.w);
        float w = g_top_w[toks[row] * 2 + k];
        sL[r * LPD + row] = v * w;
    }

    int w = tid >> 5;
    int tcol = tid & 31;
    int tb4 = w * 4;

    int buf = 0;
    for (int ci = 0; ci < 4; ci++) {
        if (ci + 1 < 4) {
            int cb = (ch0 + ci + 1) * 128;
            cpa16(sBa[buf ^ 1],       bsrc + cb);
            cpa16(sBa[buf ^ 1] + 256, bsrc + cb + 64);
            cpa_commit();
            cpa_wait1();
        } else {
            cpa_wait0();
        }
        __syncthreads();

        u64 acc[2][4];
        #pragma unroll
        for (int p = 0; p < 2; p++)
            #pragma unroll
            for (int jj = 0; jj < 4; jj++) acc[p][jj] = 0ull;

        const float* Bb = &sB[buf][0];
        #pragma unroll
        for (int r = 0; r < R; r++) {
            float4 b4 = *(const float4*)&Bb[r * BSP + tcol * 4];
            u64 b0 = pk2(b4.x, b4.x), b1 = pk2(b4.y, b4.y);
            u64 b2 = pk2(b4.z, b4.z), b3 = pk2(b4.w, b4.w);
            u64 l0 = *(const u64*)&sL[r * LPD + tb4];       // tokens tb4, tb4+1
            u64 l1 = *(const u64*)&sL[r * LPD + tb4 + 2];   // tokens tb4+2, tb4+3
            acc[0][0] = fma2(l0, b0, acc[0][0]);
            acc[0][1] = fma2(l0, b1, acc[0][1]);
            acc[0][2] = fma2(l0, b2, acc[0][2]);
            acc[0][3] = fma2(l0, b3, acc[0][3]);
            acc[1][0] = fma2(l1, b0, acc[1][0]);
            acc[1][1] = fma2(l1, b1, acc[1][1]);
            acc[1][2] = fma2(l1, b2, acc[1][2]);
            acc[1][3] = fma2(l1, b3, acc[1][3]);
        }

        int cbase = (ch0 + ci) * 128;
        #pragma unroll
        for (int p = 0; p < 2; p++) {
            float2 u0 = upk(acc[p][0]), u1 = upk(acc[p][1]);
            float2 u2 = upk(acc[p][2]), u3 = upk(acc[p][3]);
            #pragma unroll
            for (int half = 0; half < 2; half++) {
                int row = tb4 + 2 * p + half;
                if (row < nrows) {
                    float4 v = half == 0 ? make_float4(u0.x, u1.x, u2.x, u3.x)
                                         : make_float4(u0.y, u1.y, u2.y, u3.y);
                    float* pt = O + (size_t)toks[row] * ldB + cbase + tcol * 4;
                    if (k == 0) *(float4*)pt = v;
                    else        red4(pt, v);
                }
            }
        }
        __syncthreads();
        buf ^= 1;
    }
}

// ---------------- launcher ----------------
extern "C" void kernel_launch(void* const* d_in, const int* in_sizes, int n_in,
                              void* d_out, int out_size) {
    const float* h  = (const float*)d_in[0];
    const float* W  = (const float*)d_in[1];
    const float* qa = (const float*)d_in[2];
    const float* qb = (const float*)d_in[3];
    const float* va = (const float*)d_in[4];
    const float* vb = (const float*)d_in[5];
    float* out = (float*)d_out;
    int n = in_sizes[0] / D;   // 4096

    k_main<<<640, 256>>>(h, W, qa, va);
    k_route<<<(n + 127) / 128, 128>>>(n);
    dim3 gb(MAXT, 2, KSPL);
    k_low<<<gb, 128>>>(h);
    dim3 gc(MAXTD, 5);
    k_delta<<<gc, 256>>>(0, qb, vb, out);   // STG pass: writes every output
    k_delta<<<gc, 256>>>(1, qb, vb, out);   // RED pass: adds 2nd expert
}